// round 9
// baseline (speedup 1.0000x reference)
#include <cuda_runtime.h>

#define LN_EPS 1e-5f
#define Z_EPS  1e-5f

// Block-wide sum of (sum, sumsq) across 256 threads.
__device__ __forceinline__ float2 blockSum2(float2 v, float2* red) {
    const int tid  = threadIdx.x;
    const int lane = tid & 31, warp = tid >> 5;
    #pragma unroll
    for (int s = 16; s >= 1; s >>= 1) {
        v.x += __shfl_xor_sync(0xffffffffu, v.x, s);
        v.y += __shfl_xor_sync(0xffffffffu, v.y, s);
    }
    if (lane == 0) red[warp] = v;
    __syncthreads();
    if (warp == 0) {
        float2 t = (lane < 8) ? red[lane] : make_float2(0.f, 0.f);
        #pragma unroll
        for (int s = 4; s >= 1; s >>= 1) {
            t.x += __shfl_xor_sync(0xffffffffu, t.x, s);
            t.y += __shfl_xor_sync(0xffffffffu, t.y, s);
        }
        if (lane == 0) red[0] = t;
    }
    __syncthreads();
    float2 r = red[0];
    __syncthreads();
    return r;
}

__global__ __launch_bounds__(256)
void detr3d_fused_kernel(
    const float* __restrict__ query, const float* __restrict__ query_pos,
    const float* __restrict__ refp,  const float* __restrict__ l2i,
    const float* __restrict__ f0, const float* __restrict__ f1,
    const float* __restrict__ f2, const float* __restrict__ f3,
    const float* __restrict__ W_qe,   const float* __restrict__ b_qe,
    const float* __restrict__ W_attn, const float* __restrict__ b_attn,
    const float* __restrict__ W_out,  const float* __restrict__ b_out,
    const float* __restrict__ pe_w1,  const float* __restrict__ pe_b1,
    const float* __restrict__ pe_g1,  const float* __restrict__ pe_be1,
    const float* __restrict__ pe_w2,  const float* __restrict__ pe_b2,
    const float* __restrict__ pe_g2,  const float* __restrict__ pe_be2,
    const float* __restrict__ W_fin,  const float* __restrict__ b_fin,
    const float* __restrict__ g_norm, const float* __restrict__ b_norm,
    float* __restrict__ out)
{
    const int q    = blockIdx.x;           // one query per block
    const int tid  = threadIdx.x;
    const int lane = tid & 31, warp = tid >> 5;

    __shared__ float  sh_q[64];
    __shared__ float  sh_ref[3];
    __shared__ float  sh_qe[256];
    __shared__ float  sh_x[256];           // gather acc; later h = out+res+pos
    __shared__ float  sh_p[256];           // pos MLP hidden
    __shared__ float  sh_part[256];        // W_fin split-k partials
    __shared__ float2 sh_red[8];
    __shared__ float2 sh_fin[2];
    __shared__ float  sh_w[24];            // sigmoid(attw)
    __shared__ int4   sh_gi[6][4];         // clamped tap offsets
    __shared__ float4 sh_gw[6][4];         // validity-folded bilinear weights
    __shared__ int    sh_mask[6];

    // ---- load q + query_pos, reference point
    if (tid < 64) sh_q[tid] = query[q * 64 + tid] + query_pos[q * 64 + tid];
    if (tid >= 64 && tid < 67) sh_ref[tid - 64] = refp[q * 3 + (tid - 64)];
    __syncthreads();

    // ---- qe = q @ W_qe + b_qe (64 -> 256); thread = out channel
    float qe;
    {
        float a0 = 0.f, a1 = 0.f;
        #pragma unroll 8
        for (int k = 0; k < 64; k += 2) {
            a0 = fmaf(sh_q[k],     __ldg(&W_qe[k * 256 + tid]),       a0);
            a1 = fmaf(sh_q[k + 1], __ldg(&W_qe[(k + 1) * 256 + tid]), a1);
        }
        qe = __ldg(&b_qe[tid]) + a0 + a1;
        sh_qe[tid] = qe;
    }

    // ---- projection + tap precompute (threads 0..23; 1 per (n,l))
    if (tid < 24) {
        const int n = tid >> 2, l = tid & 3;
        const int Hs[4] = { 116, 58, 29, 15 };
        const int Ws[4] = { 200, 100, 50, 25 };
        const float* M = l2i + n * 16;
        const float rx = sh_ref[0], ry = sh_ref[1], rz = sh_ref[2];
        float c0 = M[0] * rx + M[1] * ry + M[2]  * rz + M[3];
        float c1 = M[4] * rx + M[5] * ry + M[6]  * rz + M[7];
        float c2 = M[8] * rx + M[9] * ry + M[10] * rz + M[11];
        bool front = c2 > Z_EPS;
        float zc = fmaxf(c2, Z_EPS);
        float gx = (c0 / zc / 1600.0f - 0.5f) * 2.0f;
        float gy = (c1 / zc / 928.0f  - 0.5f) * 2.0f;
        bool inb = (gx > -1.0f) && (gx < 1.0f) && (gy > -1.0f) && (gy < 1.0f);
        if (l == 0) sh_mask[n] = (front && inb) ? 1 : 0;

        const int W = Ws[l], H = Hs[l];
        float x = ((gx + 1.0f) * (float)W - 1.0f) * 0.5f;
        float y = ((gy + 1.0f) * (float)H - 1.0f) * 0.5f;
        float fx0 = floorf(x), fy0 = floorf(y);
        int x0 = (int)fx0, y0 = (int)fy0;
        float wx1 = x - fx0, wx0 = 1.0f - wx1;
        float wy1 = y - fy0, wy0 = 1.0f - wy1;
        float vx0 = (x0 >= 0 && x0 < W) ? 1.0f : 0.0f;
        float vx1 = (x0 + 1 >= 0 && x0 + 1 < W) ? 1.0f : 0.0f;
        float vy0 = (y0 >= 0 && y0 < H) ? 1.0f : 0.0f;
        float vy1 = (y0 + 1 >= 0 && y0 + 1 < H) ? 1.0f : 0.0f;
        int cx0 = min(max(x0, 0), W - 1);
        int cx1 = min(max(x0 + 1, 0), W - 1);
        int cy0 = min(max(y0, 0), H - 1);
        int cy1 = min(max(y0 + 1, 0), H - 1);
        sh_gi[n][l] = make_int4(cy0 * W + cx0, cy0 * W + cx1,
                                cy1 * W + cx0, cy1 * W + cx1);
        sh_gw[n][l] = make_float4(wy0 * wx0 * vy0 * vx0, wy0 * wx1 * vy0 * vx1,
                                  wy1 * wx0 * vy1 * vx0, wy1 * wx1 * vy1 * vx1);
    }
    __syncthreads();

    // ---- attw: warp-split GEMV; warp w owns outputs {w, w+8, w+16}
    {
        float a0 = 0.f, a1 = 0.f, a2 = 0.f;
        #pragma unroll
        for (int kk = 0; kk < 8; kk++) {
            const int k = lane + 32 * kk;
            const float qv = sh_qe[k];
            a0 = fmaf(qv, __ldg(&W_attn[k * 24 + warp]),      a0);
            a1 = fmaf(qv, __ldg(&W_attn[k * 24 + warp + 8]),  a1);
            a2 = fmaf(qv, __ldg(&W_attn[k * 24 + warp + 16]), a2);
        }
        #pragma unroll
        for (int s = 16; s >= 1; s >>= 1) {
            a0 += __shfl_xor_sync(0xffffffffu, a0, s);
            a1 += __shfl_xor_sync(0xffffffffu, a1, s);
            a2 += __shfl_xor_sync(0xffffffffu, a2, s);
        }
        if (lane == 0) {
            sh_w[warp]      = 1.0f / (1.0f + expf(-(a0 + __ldg(&b_attn[warp]))));
            sh_w[warp + 8]  = 1.0f / (1.0f + expf(-(a1 + __ldg(&b_attn[warp + 8]))));
            sh_w[warp + 16] = 1.0f / (1.0f + expf(-(a2 + __ldg(&b_attn[warp + 16]))));
        }
    }
    __syncthreads();

    // ---- masked bilinear gather (precomputed taps). thread = channel.
    {
        const float* fps[4] = { f0, f1, f2, f3 };
        const int HWs[4] = { 116 * 200, 58 * 100, 29 * 50, 15 * 25 };
        float acc = 0.0f;
        for (int n = 0; n < 6; n++) {
            if (!sh_mask[n]) continue;
            #pragma unroll
            for (int l = 0; l < 4; l++) {
                const int4   o = sh_gi[n][l];
                const float4 w = sh_gw[n][l];
                const float* fb = fps[l] + (size_t)(n * 256 + tid) * (size_t)HWs[l];
                float v = w.x * __ldg(fb + o.x)
                        + w.y * __ldg(fb + o.y)
                        + w.z * __ldg(fb + o.z)
                        + w.w * __ldg(fb + o.w);
                acc = fmaf(sh_w[n * 4 + l], v, acc);
            }
        }
        sh_x[tid] = acc;
    }
    __syncthreads();

    // ---- ov = acc @ W_out + b_out (256 -> 256); dual accumulators
    float ov;
    {
        float a0 = 0.f, a1 = 0.f;
        #pragma unroll 8
        for (int k = 0; k < 256; k += 2) {
            a0 = fmaf(sh_x[k],     __ldg(&W_out[k * 256 + tid]),       a0);
            a1 = fmaf(sh_x[k + 1], __ldg(&W_out[(k + 1) * 256 + tid]), a1);
        }
        ov = __ldg(&b_out[tid]) + a0 + a1;
    }

    // ---- positional MLP stage 1: ref @ pe_w1 + pe_b1 -> LN -> relu
    {
        float p = __ldg(&pe_b1[tid])
                + sh_ref[0] * __ldg(&pe_w1[tid])
                + sh_ref[1] * __ldg(&pe_w1[256 + tid])
                + sh_ref[2] * __ldg(&pe_w1[512 + tid]);
        float2 s = blockSum2(make_float2(p, p * p), sh_red);
        float m   = s.x * (1.0f / 256.0f);
        float var = s.y * (1.0f / 256.0f) - m * m;
        sh_p[tid] = fmaxf((p - m) * rsqrtf(var + LN_EPS) * __ldg(&pe_g1[tid])
                          + __ldg(&pe_be1[tid]), 0.0f);
    }
    __syncthreads();

    // ---- pos MLP stage 2: @ pe_w2 + pe_b2 -> LN -> relu; dual accumulators
    float p2;
    {
        float a0 = 0.f, a1 = 0.f;
        #pragma unroll 8
        for (int k = 0; k < 256; k += 2) {
            a0 = fmaf(sh_p[k],     __ldg(&pe_w2[k * 256 + tid]),       a0);
            a1 = fmaf(sh_p[k + 1], __ldg(&pe_w2[(k + 1) * 256 + tid]), a1);
        }
        p2 = __ldg(&pe_b2[tid]) + a0 + a1;
        float2 s = blockSum2(make_float2(p2, p2 * p2), sh_red);
        float m   = s.x * (1.0f / 256.0f);
        float var = s.y * (1.0f / 256.0f) - m * m;
        p2 = fmaxf((p2 - m) * rsqrtf(var + LN_EPS) * __ldg(&pe_g2[tid])
                   + __ldg(&pe_be2[tid]), 0.0f);
    }

    // ---- h = ov + residual(qe) + pos
    sh_x[tid] = ov + qe + p2;
    __syncthreads();

    // ---- W_fin GEMV (256 -> 64), split-k x4: tid = h*64 + c
    {
        const int h = tid >> 6, c = tid & 63;
        const int k0 = h * 64;
        float a0 = 0.f, a1 = 0.f;
        #pragma unroll 8
        for (int k = k0; k < k0 + 64; k += 2) {
            a0 = fmaf(sh_x[k],     __ldg(&W_fin[k * 64 + c]),       a0);
            a1 = fmaf(sh_x[k + 1], __ldg(&W_fin[(k + 1) * 64 + c]), a1);
        }
        sh_part[tid] = a0 + a1;
    }
    __syncthreads();

    // ---- combine 4 partials, LN over 64 channels, write out (threads 0..63)
    float y = 0.0f;
    if (tid < 64) {
        y = __ldg(&b_fin[tid]) + sh_part[tid] + sh_part[64 + tid]
          + sh_part[128 + tid] + sh_part[192 + tid];
        float sx = y, sxx = y * y;
        #pragma unroll
        for (int s = 16; s >= 1; s >>= 1) {
            sx  += __shfl_xor_sync(0xffffffffu, sx,  s);
            sxx += __shfl_xor_sync(0xffffffffu, sxx, s);
        }
        if (lane == 0) sh_fin[warp] = make_float2(sx, sxx);
    }
    __syncthreads();
    if (tid < 64) {
        float2 a = sh_fin[0], b = sh_fin[1];
        float m   = (a.x + b.x) * (1.0f / 64.0f);
        float var = (a.y + b.y) * (1.0f / 64.0f) - m * m;
        out[q * 64 + tid] =
            (y - m) * rsqrtf(var + LN_EPS) * __ldg(&g_norm[tid]) + __ldg(&b_norm[tid]);
    }
}

extern "C" void kernel_launch(void* const* d_in, const int* in_sizes, int n_in,
                              void* d_out, int out_size) {
    (void)in_sizes; (void)n_in; (void)out_size;
    const float* query     = (const float*)d_in[0];
    const float* query_pos = (const float*)d_in[1];
    const float* refp      = (const float*)d_in[2];
    const float* l2i       = (const float*)d_in[3];
    const float* f0        = (const float*)d_in[4];
    const float* f1        = (const float*)d_in[5];
    const float* f2        = (const float*)d_in[6];
    const float* f3        = (const float*)d_in[7];
    const float* W_qe      = (const float*)d_in[8];
    const float* b_qe      = (const float*)d_in[9];
    const float* W_attn    = (const float*)d_in[10];
    const float* b_attn    = (const float*)d_in[11];
    const float* W_out     = (const float*)d_in[12];
    const float* b_out     = (const float*)d_in[13];
    const float* pe_w1     = (const float*)d_in[14];
    const float* pe_b1     = (const float*)d_in[15];
    const float* pe_g1     = (const float*)d_in[16];
    const float* pe_be1    = (const float*)d_in[17];
    const float* pe_w2     = (const float*)d_in[18];
    const float* pe_b2     = (const float*)d_in[19];
    const float* pe_g2     = (const float*)d_in[20];
    const float* pe_be2    = (const float*)d_in[21];
    const float* W_fin     = (const float*)d_in[22];
    const float* b_fin     = (const float*)d_in[23];
    const float* g_norm    = (const float*)d_in[24];
    const float* b_norm    = (const float*)d_in[25];

    detr3d_fused_kernel<<<1024, 256>>>(
        query, query_pos, refp, l2i, f0, f1, f2, f3,
        W_qe, b_qe, W_attn, b_attn, W_out, b_out,
        pe_w1, pe_b1, pe_g1, pe_be1, pe_w2, pe_b2, pe_g2, pe_be2,
        W_fin, b_fin, g_norm, b_norm, (float*)d_out);
}